// round 1
// baseline (speedup 1.0000x reference)
#include <cuda_runtime.h>
#include <cuda_bf16.h>

// Problem constants
#define BB   32
#define LL   32768
#define MM   32
#define DD   128
#define KK   16
#define STR  8
#define PP   4095            // (L-K)/STR + 1
#define TP   64              // patches per CTA
#define CC   64              // c-chunk size (c-dim total = M*K = 512)
#define NCHUNK (512 / CC)    // 8
#define NTHREADS 128

// Transposed weights scratch: wT[c][d], c = k*32+m
__device__ float g_wT[512 * 128];

// ---------------------------------------------------------------------------
// Prologue: transpose conv_w (D, M, K) -> wT (C=512, D=128), coalesced writes.
// ---------------------------------------------------------------------------
__global__ void transpose_w_kernel(const float* __restrict__ w)
{
    int i = blockIdx.x * 256 + threadIdx.x;   // 0 .. 65535
    int c = i >> 7;          // 0..511
    int d = i & 127;         // 0..127
    int m = c & 31;
    int k = c >> 5;
    g_wT[i] = w[d * 512 + m * 16 + k];
}

// ---------------------------------------------------------------------------
// Main fused kernel: conv-as-GEMM + bias + sinusoidal PE (median = ts[p*8+7]).
// CTA: 64 patches x 128 d. 128 threads, each 8p x 8d register tile.
// ---------------------------------------------------------------------------
__global__ __launch_bounds__(NTHREADS)
void patch_encoder_kernel(const float* __restrict__ x,
                          const float* __restrict__ ts,
                          const float* __restrict__ bias,
                          float* __restrict__ out)
{
    extern __shared__ float smem[];
    float* xs = smem;                 // (TP*8+8)*32 = 520*32 = 16640 floats
    float* ws = smem + 16640;         // CC*128 = 8192 floats

    const int tid  = threadIdx.x;
    const int b    = blockIdx.y;
    const int p0   = blockIdx.x * TP;
    const int dblk = tid & 15;        // 16 d-blocks of 8
    const int pblk = tid >> 4;        // 8 p-blocks of 8
    const int d0   = dblk * 8;
    const int pl0  = pblk * 8;

    // ---- Load x tile: rows [p0*8, p0*8+520), 32 floats each, contiguous ----
    const float4* x4  = reinterpret_cast<const float4*>(
        x + (size_t)b * LL * MM + (size_t)p0 * 8 * MM);
    float4* xs4 = reinterpret_cast<float4*>(xs);
    const int row0 = p0 * 8;
    for (int f = tid; f < (520 * 32) / 4; f += NTHREADS) {
        int row = row0 + (f >> 3);                 // 8 float4 per row
        float4 v = make_float4(0.f, 0.f, 0.f, 0.f);
        if (row < LL) v = x4[f];
        xs4[f] = v;
    }

    float acc[8][8];
#pragma unroll
    for (int i = 0; i < 8; i++)
#pragma unroll
        for (int j = 0; j < 8; j++) acc[i][j] = 0.f;

    const float4* ws4 = reinterpret_cast<const float4*>(ws);

    for (int ch = 0; ch < NCHUNK; ch++) {
        __syncthreads();   // protect ws from previous chunk's readers / xs first use
        // ---- Load W chunk: contiguous 8192 floats = 2048 float4 ----
        const float4* wsrc = reinterpret_cast<const float4*>(g_wT + ch * CC * 128);
        float4* wdst = reinterpret_cast<float4*>(ws);
#pragma unroll
        for (int f = 0; f < 16; f++)
            wdst[tid + f * NTHREADS] = wsrc[tid + f * NTHREADS];
        __syncthreads();

        // ---- Compute: 16 steps of 4 c's ----
#pragma unroll
        for (int c4 = 0; c4 < 16; c4++) {
            float4 xv[8];
#pragma unroll
            for (int i = 0; i < 8; i++)
                xv[i] = xs4[(pl0 + i) * 64 + ch * 16 + c4];

            float4 wv[4][2];
#pragma unroll
            for (int j = 0; j < 4; j++) {
                wv[j][0] = ws4[(c4 * 4 + j) * 32 + dblk * 2];
                wv[j][1] = ws4[(c4 * 4 + j) * 32 + dblk * 2 + 1];
            }

#pragma unroll
            for (int i = 0; i < 8; i++) {
                const float xj0 = xv[i].x, xj1 = xv[i].y, xj2 = xv[i].z, xj3 = xv[i].w;
#pragma unroll
                for (int j = 0; j < 4; j++) {
                    const float xj = (j == 0) ? xj0 : (j == 1) ? xj1 : (j == 2) ? xj2 : xj3;
                    acc[i][0] += xj * wv[j][0].x;
                    acc[i][1] += xj * wv[j][0].y;
                    acc[i][2] += xj * wv[j][0].z;
                    acc[i][3] += xj * wv[j][0].w;
                    acc[i][4] += xj * wv[j][1].x;
                    acc[i][5] += xj * wv[j][1].y;
                    acc[i][6] += xj * wv[j][1].z;
                    acc[i][7] += xj * wv[j][1].w;
                }
            }
        }
    }

    // ---- Epilogue: bias + positional encoding ----
    // div_term[i] = exp(2i * (-ln(10000)/128)); here d0 is even, 4 distinct freqs.
    float freq[4];
#pragma unroll
    for (int ii = 0; ii < 4; ii++)
        freq[ii] = expf(-(float)(d0 + 2 * ii) * 0.07195578415606394f);

    float bi[8];
#pragma unroll
    for (int dd = 0; dd < 8; dd++) bi[dd] = bias[d0 + dd];

#pragma unroll
    for (int i = 0; i < 8; i++) {
        int p = p0 + pl0 + i;
        if (p >= PP) break;
        // timestamps are globally sorted along L -> window median = ts[p*8+7]
        float med = ts[(size_t)b * LL + p * 8 + 7];

        float vals[8];
#pragma unroll
        for (int ii = 0; ii < 4; ii++) {
            float s, c;
            sincosf(med * freq[ii], &s, &c);
            vals[2 * ii]     = acc[i][2 * ii]     + bi[2 * ii]     + s;
            vals[2 * ii + 1] = acc[i][2 * ii + 1] + bi[2 * ii + 1] + c;
        }

        float* op = out + ((size_t)b * PP + p) * DD + d0;
        float4 o0 = make_float4(vals[0], vals[1], vals[2], vals[3]);
        float4 o1 = make_float4(vals[4], vals[5], vals[6], vals[7]);
        reinterpret_cast<float4*>(op)[0] = o0;
        reinterpret_cast<float4*>(op)[1] = o1;
    }
}

// ---------------------------------------------------------------------------
extern "C" void kernel_launch(void* const* d_in, const int* in_sizes, int n_in,
                              void* d_out, int out_size)
{
    const float* x    = (const float*)d_in[0];   // (B, L, M)
    const float* ts   = (const float*)d_in[1];   // (B, L)
    const float* w    = (const float*)d_in[2];   // (D, M, K)
    const float* bias = (const float*)d_in[3];   // (D,)
    float* out = (float*)d_out;                  // (B, P, D)

    (void)in_sizes; (void)n_in; (void)out_size;

    transpose_w_kernel<<<256, 256>>>(w);

    const int smem_bytes = (16640 + 8192) * sizeof(float);   // 99328
    cudaFuncSetAttribute(patch_encoder_kernel,
                         cudaFuncAttributeMaxDynamicSharedMemorySize, smem_bytes);

    dim3 grid(64, BB);   // 64 p-tiles x 32 batches
    patch_encoder_kernel<<<grid, NTHREADS, smem_bytes>>>(x, ts, bias, out);
}

// round 8
// speedup vs baseline: 2.6925x; 2.6925x over previous
#include <cuda_runtime.h>
#include <cuda_bf16.h>
#include <cstdint>

#define BB 32
#define LL 32768
#define PP 4095
#define DD 128
#define NT 256
#define SAW 36   // smem row stride in 32-bit words (72 bf16 = 144 B) -> conflict-free

// bf16 hi/lo weight planes, layout [d][c], c = k*32+m (K-major rows)
__device__ __align__(16) __nv_bfloat16 g_w_hi[128 * 512];
__device__ __align__(16) __nv_bfloat16 g_w_lo[128 * 512];

// ---------------------------------------------------------------------------
// Prologue: conv_w (D, M, K) -> W[d][c] = w[d, c%32, c/32], split hi/lo bf16.
// ---------------------------------------------------------------------------
__global__ void prep_w_kernel(const float* __restrict__ w)
{
    int i = blockIdx.x * 256 + threadIdx.x;   // 0 .. 65535
    int d = i >> 9, c = i & 511;
    int m = c & 31, kc = c >> 5;
    float v = w[d * 512 + m * 16 + kc];
    __nv_bfloat16 h = __float2bfloat16(v);
    g_w_hi[i] = h;
    g_w_lo[i] = __float2bfloat16(v - __bfloat162float(h));
}

// m16n8k16 row.col bf16 MMA, f32 accumulate in-place
#define MMA_BF16(D, A, B0, B1)                                            \
    asm volatile("mma.sync.aligned.m16n8k16.row.col.f32.bf16.bf16.f32 "   \
        "{%0,%1,%2,%3}, {%4,%5,%6,%7}, {%8,%9}, {%0,%1,%2,%3};"           \
        : "+f"((D)[0]), "+f"((D)[1]), "+f"((D)[2]), "+f"((D)[3])          \
        : "r"((A)[0]), "r"((A)[1]), "r"((A)[2]), "r"((A)[3]),             \
          "r"(B0), "r"(B1))

// ---------------------------------------------------------------------------
// Main kernel: HMMA bf16x3 GEMM + bias + sinusoidal PE (median = ts[8p+7])
// CTA: 128 patches x 128 D, 8 warps (4 m-blocks x 2 n-blocks), warp 32x64.
// ---------------------------------------------------------------------------
__global__ __launch_bounds__(NT, 2)
void pe_mma(const float* __restrict__ x, const float* __restrict__ ts,
            const float* __restrict__ bias, float* __restrict__ out)
{
    extern __shared__ __align__(16) uint32_t sw[];
    uint32_t* Ah = sw;             // 128*36 = 4608 words
    uint32_t* Al = sw + 4608;
    uint32_t* Bh = sw + 9216;
    uint32_t* Bl = sw + 13824;     // total 18432 words = 73728 B

    const int tid  = threadIdx.x, wid = tid >> 5, lane = tid & 31;
    const int gid  = lane >> 2, tig = lane & 3;
    const int b    = blockIdx.y;
    const int p0   = blockIdx.x * 128;
    const int wm   = (wid & 3) * 32;   // warp m-base (patches)
    const int wn   = (wid >> 2) * 64;  // warp n-base (d)
    const float* xb = x + (size_t)b * (LL * 32);

    float acc[2][8][4];
#pragma unroll
    for (int mt = 0; mt < 2; mt++)
#pragma unroll
        for (int nt = 0; nt < 8; nt++)
#pragma unroll
            for (int q = 0; q < 4; q++) acc[mt][nt][q] = 0.f;

    for (int ch = 0; ch < 8; ch++) {
        __syncthreads();
        // ---- A tile: 128 patch-rows x 64 fp32 (contiguous in x), hi/lo split ----
#pragma unroll
        for (int i = 0; i < 8; i++) {
            int f = tid + i * NT;            // 0..2047 (128 rows x 16 float4)
            int row = f >> 4, c4 = f & 15;
            int p = p0 + row;
            float4 v = make_float4(0.f, 0.f, 0.f, 0.f);
            if (p < PP)
                v = *(const float4*)(xb + (size_t)(8 * p + 2 * ch) * 32 + c4 * 4);
            __nv_bfloat162 h01 = __floats2bfloat162_rn(v.x, v.y);
            __nv_bfloat162 h23 = __floats2bfloat162_rn(v.z, v.w);
            float lx = v.x - __bfloat162float(__low2bfloat16(h01));
            float ly = v.y - __bfloat162float(__high2bfloat16(h01));
            float lz = v.z - __bfloat162float(__low2bfloat16(h23));
            float lw = v.w - __bfloat162float(__high2bfloat16(h23));
            __nv_bfloat162 l01 = __floats2bfloat162_rn(lx, ly);
            __nv_bfloat162 l23 = __floats2bfloat162_rn(lz, lw);
            uint32_t off = row * SAW + c4 * 2;   // word index
            *(uint2*)(Ah + off) = make_uint2(*(uint32_t*)&h01, *(uint32_t*)&h23);
            *(uint2*)(Al + off) = make_uint2(*(uint32_t*)&l01, *(uint32_t*)&l23);
        }
        // ---- B tiles: 128 d-rows x 64 bf16 each plane (L2-resident) ----
#pragma unroll
        for (int i = 0; i < 8; i++) {
            int f = tid + i * NT;            // 0..2047 (128 rows x 16 uint2)
            int d = f >> 4, q = f & 15;
            uint32_t off = d * SAW + q * 2;
            *(uint2*)(Bh + off) = ((const uint2*)(g_w_hi + d * 512 + ch * 64))[q];
            *(uint2*)(Bl + off) = ((const uint2*)(g_w_lo + d * 512 + ch * 64))[q];
        }
        __syncthreads();

        // ---- Compute: 4 k16-steps x 3 products x (2 m-tiles x 8 n-tiles) ----
#pragma unroll
        for (int k16 = 0; k16 < 4; k16++) {
            const int kw2 = k16 * 8 + tig;   // word offset within row
            uint32_t ah[2][4], al[2][4];
#pragma unroll
            for (int mt = 0; mt < 2; mt++) {
                int r = wm + mt * 16 + gid;
                ah[mt][0] = Ah[r * SAW + kw2];
                ah[mt][1] = Ah[(r + 8) * SAW + kw2];
                ah[mt][2] = Ah[r * SAW + kw2 + 4];
                ah[mt][3] = Ah[(r + 8) * SAW + kw2 + 4];
                al[mt][0] = Al[r * SAW + kw2];
                al[mt][1] = Al[(r + 8) * SAW + kw2];
                al[mt][2] = Al[r * SAW + kw2 + 4];
                al[mt][3] = Al[(r + 8) * SAW + kw2 + 4];
            }
#pragma unroll
            for (int nt = 0; nt < 8; nt++) {
                int n = wn + nt * 8 + gid;
                uint32_t bh0 = Bh[n * SAW + kw2], bh1 = Bh[n * SAW + kw2 + 4];
                uint32_t bl0 = Bl[n * SAW + kw2], bl1 = Bl[n * SAW + kw2 + 4];
                MMA_BF16(acc[0][nt], ah[0], bh0, bh1);   // hi*hi
                MMA_BF16(acc[1][nt], ah[1], bh0, bh1);
                MMA_BF16(acc[0][nt], ah[0], bl0, bl1);   // hi*lo
                MMA_BF16(acc[1][nt], ah[1], bl0, bl1);
                MMA_BF16(acc[0][nt], al[0], bh0, bh1);   // lo*hi
                MMA_BF16(acc[1][nt], al[1], bh0, bh1);
            }
        }
    }

    // ---- Epilogue: bias + positional encoding, fused store ----
    float  freqs[8];
    float2 bi[8];
#pragma unroll
    for (int nt = 0; nt < 8; nt++) {
        int d0 = wn + nt * 8 + tig * 2;    // even
        freqs[nt] = __expf(-(float)d0 * 0.07195578415606394f);
        bi[nt] = *(const float2*)(bias + d0);
    }
#pragma unroll
    for (int mt = 0; mt < 2; mt++) {
#pragma unroll
        for (int h = 0; h < 2; h++) {
            int p = p0 + wm + mt * 16 + h * 8 + gid;
            if (p < PP) {
                // timestamps sorted along L -> window median = ts[p*8+7]
                float med = ts[(size_t)b * LL + p * 8 + 7];
                float* op = out + ((size_t)b * PP + p) * DD;
#pragma unroll
                for (int nt = 0; nt < 8; nt++) {
                    float s, c;
                    __sincosf(med * freqs[nt], &s, &c);
                    float2 v;
                    v.x = acc[mt][nt][h * 2 + 0] + bi[nt].x + s;
                    v.y = acc[mt][nt][h * 2 + 1] + bi[nt].y + c;
                    *(float2*)(op + wn + nt * 8 + tig * 2) = v;
                }
            }
        }
    }
}

// ---------------------------------------------------------------------------
extern "C" void kernel_launch(void* const* d_in, const int* in_sizes, int n_in,
                              void* d_out, int out_size)
{
    const float* x    = (const float*)d_in[0];   // (B, L, M)
    const float* ts   = (const float*)d_in[1];   // (B, L)
    const float* w    = (const float*)d_in[2];   // (D, M, K)
    const float* bias = (const float*)d_in[3];   // (D,)
    float* out = (float*)d_out;                  // (B, P, D)
    (void)in_sizes; (void)n_in; (void)out_size;

    prep_w_kernel<<<256, 256>>>(w);

    const int smem_bytes = 18432 * 4;   // 73728
    cudaFuncSetAttribute(pe_mma,
                         cudaFuncAttributeMaxDynamicSharedMemorySize, smem_bytes);
    dim3 grid(32, BB);   // 32 p-tiles x 32 batches
    pe_mma<<<grid, NT, smem_bytes>>>(x, ts, bias, out);
}

// round 9
// speedup vs baseline: 2.8214x; 1.0478x over previous
#include <cuda_runtime.h>
#include <cuda_bf16.h>
#include <cstdint>

#define BB 32
#define LL 32768
#define PP 4095
#define DD 128
#define NT 256
#define NCH 16          // K chunks of 32 (total K = 512)
#define RS 20           // smem row stride in words (16 data + 4 pad) -> conflict-free
// Stage layout (words): Ah[128*20] Al[128*20] Bh[128*20] Bl[128*20] = 10240 words = 40KB
#define PL 2560         // plane size in words
#define STW 10240       // stage stride in words

// bf16 hi/lo weight planes, layout [d][c], c = k*32+m (K-major rows)
__device__ __align__(16) __nv_bfloat16 g_w_hi[128 * 512];
__device__ __align__(16) __nv_bfloat16 g_w_lo[128 * 512];

__global__ void prep_w_kernel(const float* __restrict__ w)
{
    int i = blockIdx.x * 256 + threadIdx.x;   // 0 .. 65535
    int d = i >> 9, c = i & 511;
    int m = c & 31, kc = c >> 5;
    float v = w[d * 512 + m * 16 + kc];
    __nv_bfloat16 h = __float2bfloat16(v);
    g_w_hi[i] = h;
    g_w_lo[i] = __float2bfloat16(v - __bfloat162float(h));
}

#define MMA_BF16(D, A, B0, B1)                                            \
    asm volatile("mma.sync.aligned.m16n8k16.row.col.f32.bf16.bf16.f32 "   \
        "{%0,%1,%2,%3}, {%4,%5,%6,%7}, {%8,%9}, {%0,%1,%2,%3};"           \
        : "+f"((D)[0]), "+f"((D)[1]), "+f"((D)[2]), "+f"((D)[3])          \
        : "r"((A)[0]), "r"((A)[1]), "r"((A)[2]), "r"((A)[3]),             \
          "r"(B0), "r"(B1))

#define CP16(dst, src) \
    asm volatile("cp.async.cg.shared.global [%0], [%1], 16;" :: "r"(dst), "l"(src) : "memory")
#define CP_COMMIT asm volatile("cp.async.commit_group;" ::: "memory")
#define CP_WAIT0  asm volatile("cp.async.wait_group 0;"  ::: "memory")

__device__ __forceinline__ uint32_t smem_u32(const void* p) {
    uint32_t a;
    asm("{ .reg .u64 t; cvta.to.shared.u64 t, %1; cvt.u32.u64 %0, t; }" : "=r"(a) : "l"(p));
    return a;
}

// ---------------------------------------------------------------------------
// HMMA bf16x3 GEMM + bias + PE. CTA 128p x 128d, 8 warps (4m x 2n), warp 32x64.
// Double-buffered 32-c chunks; cp.async B, register-prefetched A.
// ---------------------------------------------------------------------------
__global__ __launch_bounds__(NT, 2)
void pe_mma(const float* __restrict__ x, const float* __restrict__ ts,
            const float* __restrict__ bias, float* __restrict__ out)
{
    extern __shared__ __align__(16) uint32_t sw[];
    const uint32_t sb = smem_u32(sw);

    const int tid  = threadIdx.x, wid = tid >> 5, lane = tid & 31;
    const int gid  = lane >> 2, tig = lane & 3;
    const int b    = blockIdx.y;
    const int p0   = blockIdx.x * 128;
    const int wm   = (wid & 3) * 32;   // warp m-base (patches)
    const int wn   = (wid >> 2) * 64;  // warp n-base (d)
    const float* xb = x + (size_t)b * (LL * 32);

    // Per-thread load geometry
    const int arow = tid >> 3, ac4 = tid & 7;            // A: 2 rows/thread (arow, arow+32.. no: f=tid+i*256)
    // B cp.async: f = tid + i*256 -> plane = f>>9 ... computed inline.

    float acc[2][8][4];
#pragma unroll
    for (int mt = 0; mt < 2; mt++)
#pragma unroll
        for (int nt = 0; nt < 8; nt++)
#pragma unroll
            for (int q = 0; q < 4; q++) acc[mt][nt][q] = 0.f;

    float4 av[4];

    // ---- helpers as lambdas ----
    auto loadA = [&](int ch) {
#pragma unroll
        for (int i = 0; i < 4; i++) {
            int f = tid + i * NT;            // 0..1023 : row = f>>3 (8 float4/row)
            int row = f >> 3, c4 = f & 7;
            int p = p0 + row;
            av[i] = make_float4(0.f, 0.f, 0.f, 0.f);
            if (p < PP)
                av[i] = *(const float4*)(xb + (size_t)p * 256 + ch * 32 + c4 * 4);
        }
    };
    auto cpB = [&](int ch, int s) {
#pragma unroll
        for (int i = 0; i < 4; i++) {
            int f = tid + i * NT;            // 0..1023
            int plane = f >> 9;              // 0 hi, 1 lo (512 segs each)
            int g = f & 511;
            int d = g >> 2, seg = g & 3;     // 4 x 16B per row
            uint32_t dst = sb + (s * STW + (2 + plane) * PL) * 4 + d * (RS * 4) + seg * 16;
            const __nv_bfloat16* src =
                (plane ? g_w_lo : g_w_hi) + d * 512 + ch * 32 + seg * 8;
            CP16(dst, src);
        }
        CP_COMMIT;
    };
    auto stsA = [&](int s) {
        uint32_t* Ah = sw + s * STW;
        uint32_t* Al = Ah + PL;
#pragma unroll
        for (int i = 0; i < 4; i++) {
            int f = tid + i * NT;
            int row = f >> 3, c4 = f & 7;
            float4 v = av[i];
            __nv_bfloat162 h01 = __floats2bfloat162_rn(v.x, v.y);
            __nv_bfloat162 h23 = __floats2bfloat162_rn(v.z, v.w);
            float lx = v.x - __bfloat162float(__low2bfloat16(h01));
            float ly = v.y - __bfloat162float(__high2bfloat16(h01));
            float lz = v.z - __bfloat162float(__low2bfloat16(h23));
            float lw = v.w - __bfloat162float(__high2bfloat16(h23));
            __nv_bfloat162 l01 = __floats2bfloat162_rn(lx, ly);
            __nv_bfloat162 l23 = __floats2bfloat162_rn(lz, lw);
            uint32_t off = row * RS + c4 * 2;
            *(uint2*)(Ah + off) = make_uint2(*(uint32_t*)&h01, *(uint32_t*)&h23);
            *(uint2*)(Al + off) = make_uint2(*(uint32_t*)&l01, *(uint32_t*)&l23);
        }
    };

    // ---- prologue: fill stage 0 with chunk 0 ----
    loadA(0);
    cpB(0, 0);
    stsA(0);
    CP_WAIT0;
    __syncthreads();

#pragma unroll 2
    for (int ch = 0; ch < NCH; ch++) {
        const int s = ch & 1;
        if (ch + 1 < NCH) {
            loadA(ch + 1);        // LDGs issue now, land during compute
            cpB(ch + 1, s ^ 1);
        }

        // ---- compute chunk ch from stage s ----
        {
            const uint32_t* Ah = sw + s * STW;
            const uint32_t* Al = Ah + PL;
            const uint32_t* Bh = Ah + 2 * PL;
            const uint32_t* Bl = Ah + 3 * PL;
#pragma unroll
            for (int k16 = 0; k16 < 2; k16++) {
                const int kw2 = k16 * 8 + tig;
                uint32_t ah[2][4], al[2][4];
#pragma unroll
                for (int mt = 0; mt < 2; mt++) {
                    int r = wm + mt * 16 + gid;
                    ah[mt][0] = Ah[r * RS + kw2];
                    ah[mt][1] = Ah[(r + 8) * RS + kw2];
                    ah[mt][2] = Ah[r * RS + kw2 + 4];
                    ah[mt][3] = Ah[(r + 8) * RS + kw2 + 4];
                    al[mt][0] = Al[r * RS + kw2];
                    al[mt][1] = Al[(r + 8) * RS + kw2];
                    al[mt][2] = Al[r * RS + kw2 + 4];
                    al[mt][3] = Al[(r + 8) * RS + kw2 + 4];
                }
#pragma unroll
                for (int nt = 0; nt < 8; nt++) {
                    int n = wn + nt * 8 + gid;
                    uint32_t bh0 = Bh[n * RS + kw2], bh1 = Bh[n * RS + kw2 + 4];
                    uint32_t bl0 = Bl[n * RS + kw2], bl1 = Bl[n * RS + kw2 + 4];
                    MMA_BF16(acc[0][nt], ah[0], bh0, bh1);
                    MMA_BF16(acc[1][nt], ah[1], bh0, bh1);
                    MMA_BF16(acc[0][nt], ah[0], bl0, bl1);
                    MMA_BF16(acc[1][nt], ah[1], bl0, bl1);
                    MMA_BF16(acc[0][nt], al[0], bh0, bh1);
                    MMA_BF16(acc[1][nt], al[1], bh0, bh1);
                }
            }
        }

        if (ch + 1 < NCH) {
            stsA(s ^ 1);
            CP_WAIT0;
        }
        __syncthreads();
    }

    // ---- Epilogue: bias + positional encoding ----
    float  freqs[8];
    float2 bi[8];
#pragma unroll
    for (int nt = 0; nt < 8; nt++) {
        int d0 = wn + nt * 8 + tig * 2;
        freqs[nt] = __expf(-(float)d0 * 0.07195578415606394f);
        bi[nt] = *(const float2*)(bias + d0);
    }
#pragma unroll
    for (int mt = 0; mt < 2; mt++) {
#pragma unroll
        for (int h = 0; h < 2; h++) {
            int p = p0 + wm + mt * 16 + h * 8 + gid;
            if (p < PP) {
                // timestamps sorted along L -> window median = ts[p*8+7]
                float med = ts[(size_t)b * LL + p * 8 + 7];
                float* op = out + ((size_t)b * PP + p) * DD;
#pragma unroll
                for (int nt = 0; nt < 8; nt++) {
                    float s, c;
                    __sincosf(med * freqs[nt], &s, &c);
                    float2 v;
                    v.x = acc[mt][nt][h * 2 + 0] + bi[nt].x + s;
                    v.y = acc[mt][nt][h * 2 + 1] + bi[nt].y + c;
                    *(float2*)(op + wn + nt * 8 + tig * 2) = v;
                }
            }
        }
    }
}

// ---------------------------------------------------------------------------
extern "C" void kernel_launch(void* const* d_in, const int* in_sizes, int n_in,
                              void* d_out, int out_size)
{
    const float* x    = (const float*)d_in[0];   // (B, L, M)
    const float* ts   = (const float*)d_in[1];   // (B, L)
    const float* w    = (const float*)d_in[2];   // (D, M, K)
    const float* bias = (const float*)d_in[3];   // (D,)
    float* out = (float*)d_out;                  // (B, P, D)
    (void)in_sizes; (void)n_in; (void)out_size;

    prep_w_kernel<<<256, 256>>>(w);

    const int smem_bytes = 2 * STW * 4;   // 81920 per CTA
    cudaFuncSetAttribute(pe_mma,
                         cudaFuncAttributeMaxDynamicSharedMemorySize, smem_bytes);
    dim3 grid(32, BB);   // 32 p-tiles x 32 batches
    pe_mma<<<grid, NT, smem_bytes>>>(x, ts, bias, out);
}

// round 10
// speedup vs baseline: 4.1187x; 1.4598x over previous
#include <cuda_runtime.h>
#include <cuda_fp16.h>
#include <cstdint>

#define BB 32
#define LL 32768
#define PP 4095
#define DD 128
#define NT 256
#define NCH 16          // K chunks of 32 (total K = 512)
#define RSB 80          // smem row stride bytes (64 data + 16 pad) -> ldmatrix conflict-free
// Stage: Ah[128*80] Al[128*80] Bw[128*80] = 30720 B; 2 stages = 61440 B
#define PLB 10240
#define STB 30720

// fp16 weight plane, layout [d][c], c = k*32+m (K-major rows)
__device__ __align__(16) __half g_w[128 * 512];

__global__ void prep_w_kernel(const float* __restrict__ w)
{
    int i = blockIdx.x * 256 + threadIdx.x;   // 0 .. 65535
    int d = i >> 9, c = i & 511;
    int m = c & 31, kc = c >> 5;
    g_w[i] = __float2half_rn(w[d * 512 + m * 16 + kc]);
}

#define MMA_F16(D, A, B0, B1)                                             \
    asm volatile("mma.sync.aligned.m16n8k16.row.col.f32.f16.f16.f32 "     \
        "{%0,%1,%2,%3}, {%4,%5,%6,%7}, {%8,%9}, {%0,%1,%2,%3};"           \
        : "+f"((D)[0]), "+f"((D)[1]), "+f"((D)[2]), "+f"((D)[3])          \
        : "r"((A)[0]), "r"((A)[1]), "r"((A)[2]), "r"((A)[3]),             \
          "r"(B0), "r"(B1))

#define LDM_X4(R, ADDR)                                                   \
    asm volatile("ldmatrix.sync.aligned.m8n8.x4.shared.b16 "              \
        "{%0,%1,%2,%3}, [%4];"                                            \
        : "=r"((R)[0]), "=r"((R)[1]), "=r"((R)[2]), "=r"((R)[3])          \
        : "r"(ADDR))

#define CP16(dst, src) \
    asm volatile("cp.async.cg.shared.global [%0], [%1], 16;" :: "r"(dst), "l"(src) : "memory")
#define CP_COMMIT asm volatile("cp.async.commit_group;" ::: "memory")
#define CP_WAIT0  asm volatile("cp.async.wait_group 0;"  ::: "memory")

__device__ __forceinline__ uint32_t smem_u32(const void* p) {
    uint32_t a;
    asm("{ .reg .u64 t; cvta.to.shared.u64 t, %1; cvt.u32.u64 %0, t; }" : "=r"(a) : "l"(p));
    return a;
}

// ---------------------------------------------------------------------------
// HMMA fp16x2 GEMM + bias + PE. CTA 128p x 128d, 8 warps (4m x 2n), warp 32x64.
// x split hi/lo fp16 (LDG+cvt+STS), W single fp16 plane (cp.async).
// All operand loads via ldmatrix.x4. Double-buffered 32-c chunks.
// ---------------------------------------------------------------------------
__global__ __launch_bounds__(NT, 2)
void pe_mma(const float* __restrict__ x, const float* __restrict__ ts,
            const float* __restrict__ bias, float* __restrict__ out)
{
    extern __shared__ __align__(16) char smem[];
    const uint32_t sb = smem_u32(smem);

    const int tid  = threadIdx.x, wid = tid >> 5, lane = tid & 31;
    const int gid  = lane >> 2, tig = lane & 3;
    const int b    = blockIdx.y;
    const int p0   = blockIdx.x * 128;
    const int wm   = (wid & 3) * 32;   // warp m-base (patches)
    const int wn   = (wid >> 2) * 64;  // warp n-base (d)
    const float* xb = x + (size_t)b * (LL * 32);

    // ldmatrix lane geometry (m = lane>>3 selects the 4 sub-matrices)
    const int a_row = (lane & 7) + 8 * ((lane >> 3) & 1);
    const int a_seg = lane >> 4;            // k-half
    const int b_row = (lane & 7) + 8 * (lane >> 4);
    const int b_seg = (lane >> 3) & 1;      // k-half

    float acc[2][8][4];
#pragma unroll
    for (int mt = 0; mt < 2; mt++)
#pragma unroll
        for (int nt = 0; nt < 8; nt++)
#pragma unroll
            for (int q = 0; q < 4; q++) acc[mt][nt][q] = 0.f;

    float4 av[4];

    auto loadA = [&](int ch) {
#pragma unroll
        for (int i = 0; i < 4; i++) {
            int f = tid + i * NT;            // 0..1023: 128 rows x 8 float4
            int row = f >> 3, c4 = f & 7;
            int p = p0 + row;
            av[i] = make_float4(0.f, 0.f, 0.f, 0.f);
            if (p < PP)
                av[i] = *(const float4*)(xb + (size_t)p * 256 + ch * 32 + c4 * 4);
        }
    };
    auto cpB = [&](int ch, int s) {
#pragma unroll
        for (int i = 0; i < 2; i++) {
            int f = tid + i * NT;            // 0..511: 128 rows x 4 seg16
            int d = f >> 2, seg = f & 3;
            uint32_t dst = sb + s * STB + 2 * PLB + d * RSB + seg * 16;
            CP16(dst, g_w + d * 512 + ch * 32 + seg * 8);
        }
        CP_COMMIT;
    };
    auto stsA = [&](int s) {
        char* Ah = smem + s * STB;
        char* Al = Ah + PLB;
#pragma unroll
        for (int i = 0; i < 4; i++) {
            int f = tid + i * NT;
            int row = f >> 3, c4 = f & 7;
            float4 v = av[i];
            __half2 h01 = __floats2half2_rn(v.x, v.y);
            __half2 h23 = __floats2half2_rn(v.z, v.w);
            float lx = v.x - __half2float(__low2half(h01));
            float ly = v.y - __half2float(__high2half(h01));
            float lz = v.z - __half2float(__low2half(h23));
            float lw = v.w - __half2float(__high2half(h23));
            __half2 l01 = __floats2half2_rn(lx, ly);
            __half2 l23 = __floats2half2_rn(lz, lw);
            uint32_t off = row * RSB + c4 * 8;
            *(uint2*)(Ah + off) = make_uint2(*(uint32_t*)&h01, *(uint32_t*)&h23);
            *(uint2*)(Al + off) = make_uint2(*(uint32_t*)&l01, *(uint32_t*)&l23);
        }
    };

    // ---- prologue: fill stage 0 with chunk 0 ----
    loadA(0);
    cpB(0, 0);
    stsA(0);
    CP_WAIT0;
    __syncthreads();

    for (int ch = 0; ch < NCH; ch++) {
        const int s = ch & 1;
        if (ch + 1 < NCH) {
            loadA(ch + 1);        // LDGs land during compute
            cpB(ch + 1, s ^ 1);
        }

        // ---- compute chunk ch from stage s ----
        {
            const uint32_t Ah = sb + s * STB;
            const uint32_t Al = Ah + PLB;
            const uint32_t Bw = Ah + 2 * PLB;
#pragma unroll
            for (int t = 0; t < 2; t++) {
                uint32_t ah[2][4], al[2][4], bw[4][4];
#pragma unroll
                for (int mt = 0; mt < 2; mt++) {
                    uint32_t ar = Ah + (wm + mt * 16 + a_row) * RSB + (t * 2 + a_seg) * 16;
                    LDM_X4(ah[mt], ar);
                    LDM_X4(al[mt], ar + PLB);
                }
#pragma unroll
                for (int j = 0; j < 4; j++) {
                    uint32_t br = Bw + (wn + j * 16 + b_row) * RSB + (t * 2 + b_seg) * 16;
                    LDM_X4(bw[j], br);
                }
#pragma unroll
                for (int nt = 0; nt < 8; nt++) {
                    uint32_t b0 = bw[nt >> 1][(nt & 1) * 2];
                    uint32_t b1 = bw[nt >> 1][(nt & 1) * 2 + 1];
                    MMA_F16(acc[0][nt], ah[0], b0, b1);
                    MMA_F16(acc[1][nt], ah[1], b0, b1);
                    MMA_F16(acc[0][nt], al[0], b0, b1);
                    MMA_F16(acc[1][nt], al[1], b0, b1);
                }
            }
        }

        if (ch + 1 < NCH) {
            stsA(s ^ 1);
            CP_WAIT0;
        }
        __syncthreads();
    }

    // ---- Epilogue: bias + positional encoding ----
    float  freqs[8];
    float2 bi[8];
#pragma unroll
    for (int nt = 0; nt < 8; nt++) {
        int d0 = wn + nt * 8 + tig * 2;
        freqs[nt] = __expf(-(float)d0 * 0.07195578415606394f);
        bi[nt] = *(const float2*)(bias + d0);
    }
#pragma unroll
    for (int mt = 0; mt < 2; mt++) {
#pragma unroll
        for (int h = 0; h < 2; h++) {
            int p = p0 + wm + mt * 16 + h * 8 + gid;
            if (p < PP) {
                // timestamps sorted along L -> window median = ts[p*8+7]
                float med = ts[(size_t)b * LL + p * 8 + 7];
                float* op = out + ((size_t)b * PP + p) * DD;
#pragma unroll
                for (int nt = 0; nt < 8; nt++) {
                    float s, c;
                    __sincosf(med * freqs[nt], &s, &c);
                    float2 v;
                    v.x = acc[mt][nt][h * 2 + 0] + bi[nt].x + s;
                    v.y = acc[mt][nt][h * 2 + 1] + bi[nt].y + c;
                    *(float2*)(op + wn + nt * 8 + tig * 2) = v;
                }
            }
        }
    }
}

// ---------------------------------------------------------------------------
extern "C" void kernel_launch(void* const* d_in, const int* in_sizes, int n_in,
                              void* d_out, int out_size)
{
    const float* x    = (const float*)d_in[0];   // (B, L, M)
    const float* ts   = (const float*)d_in[1];   // (B, L)
    const float* w    = (const float*)d_in[2];   // (D, M, K)
    const float* bias = (const float*)d_in[3];   // (D,)
    float* out = (float*)d_out;                  // (B, P, D)
    (void)in_sizes; (void)n_in; (void)out_size;

    prep_w_kernel<<<256, 256>>>(w);

    const int smem_bytes = 2 * STB;   // 61440
    cudaFuncSetAttribute(pe_mma,
                         cudaFuncAttributeMaxDynamicSharedMemorySize, smem_bytes);
    dim3 grid(32, BB);   // 32 p-tiles x 32 batches
    pe_mma<<<grid, NT, smem_bytes>>>(x, ts, bias, out);
}